// round 1
// baseline (speedup 1.0000x reference)
#include <cuda_runtime.h>
#include <cuda_bf16.h>

// TransientCombNoise: B=32, T=2000, BLOCK=64, MAX_DELAY=480, SR=16000.
// Per row r (of N = 64000): from params[r] = (p0,p1,p2,p3):
//   att    = max(16000*(0.0005 + p0*0.0495), 1)
//   energy = p1 ; tilt = 2*p2 - 1
//   bw     = 0.05 + p3*0.95 ; delay = clip(int(64*(0.5+0.5*bw)), 1, 480)  -> in [33,63]
//   x[i]   = noise[r,i] * exp(-i/att) * energy
//   y[i]   = x[i] + tilt * x[i-delay]   (tap only valid for i >= delay; delay>=33 => single tap)
//   out    = y / sqrt(mean(y^2) + 1e-5)
//
// One warp per row, lane handles elements i and i+32. The tap index
// (lane+32-delay) is always in [-31, 30] => one __shfl_sync from a lane's
// first element. Fully coalesced, memory-bound kernel.

#define N_ROWS (32 * 2000)

__global__ __launch_bounds__(256) void tcn_kernel(
    const float* __restrict__ params,   // [N_ROWS, 4]
    const float* __restrict__ noise,    // [N_ROWS, 64]
    float* __restrict__ out)            // [N_ROWS, 64]
{
    const int warp = (blockIdx.x * blockDim.x + threadIdx.x) >> 5;
    const int lane = threadIdx.x & 31;
    if (warp >= N_ROWS) return;

    // All lanes load the same 16B -> single broadcast transaction.
    const float4 p = *reinterpret_cast<const float4*>(params + (size_t)warp * 4);

    // Strict-rounded ops so delay matches JAX's unfused fp32 arithmetic.
    const float att    = fmaxf(__fmul_rn(16000.0f,
                               __fadd_rn(0.0005f, __fmul_rn(p.x, 0.0495f))), 1.0f);
    const float energy = p.y;
    const float tilt   = __fmaf_rn(p.z, 2.0f, -1.0f);   // 2*p.z exact, so == mul+add
    const float bw     = __fadd_rn(0.05f, __fmul_rn(p.w, 0.95f));
    int delay = (int)__fmul_rn(64.0f, __fadd_rn(0.5f, __fmul_rn(0.5f, bw)));
    delay = min(max(delay, 1), 480);

    const float inv_att = __frcp_rn(att);
    const size_t base = (size_t)warp * 64 + lane;

    // burst = noise * envelope * energy
    const float e0 = __expf(-(float)lane * inv_att);
    const float e1 = __expf(-(float)(lane + 32) * inv_att);
    const float x0 = noise[base]      * e0 * energy;
    const float x1 = noise[base + 32] * e1 * energy;

    // Comb: tap index for element (lane+32) is j = lane+32-delay in [-31, 30].
    // When valid (j >= 0), the tap value is lane j's x0. Element `lane` never
    // has a valid tap (lane <= 31 < 33 <= delay).
    const int j = lane + 32 - delay;
    const float tap = __shfl_sync(0xFFFFFFFFu, x0, j & 31);
    const float y0 = x0;
    const float y1 = (j >= 0) ? __fmaf_rn(tilt, tap, x1) : x1;

    // RMS over 64 samples (warp reduction).
    float ss = y0 * y0 + y1 * y1;
    #pragma unroll
    for (int o = 16; o > 0; o >>= 1)
        ss += __shfl_xor_sync(0xFFFFFFFFu, ss, o);

    const float inv_rms = rsqrtf(ss * (1.0f / 64.0f) + 1e-5f);

    out[base]      = y0 * inv_rms;
    out[base + 32] = y1 * inv_rms;
}

extern "C" void kernel_launch(void* const* d_in, const int* in_sizes, int n_in,
                              void* d_out, int out_size)
{
    const float* params = (const float*)d_in[0];  // [32,2000,4]
    const float* noise  = (const float*)d_in[1];  // [32,2000,64]
    float* out = (float*)d_out;                   // [32, 2000*64]

    const int warps_per_block = 8;                // 256 threads
    const int blocks = (N_ROWS + warps_per_block - 1) / warps_per_block;  // 8000
    tcn_kernel<<<blocks, warps_per_block * 32>>>(params, noise, out);
}

// round 2
// speedup vs baseline: 1.0435x; 1.0435x over previous
#include <cuda_runtime.h>
#include <cuda_bf16.h>

// TransientCombNoise: B=32, T=2000, BLOCK=64, MAX_DELAY=480, SR=16000.
// Per row r of N=64000, params (p0..p3):
//   att   = max(16000*(0.0005 + p0*0.0495), 1)   (>= 8)
//   energy= p1 ; tilt = 2*p2 - 1
//   delay = int(64*(0.5 + 0.5*(0.05 + 0.95*p3)))  in [33, 63]
//   x[i]  = noise[i] * exp(-i/att) * energy
//   y[i]  = x[i] + tilt * x[i-delay]          (single feed-forward tap: delay>=33)
//   out   = y * rsqrt(mean(y^2) + 1e-5)
//
// Factorization: env(i-d) = env(i)*exp(d/att), so
//   y[i] = env(i)*energy*( noise[i] + tilt*exp(d/att)*noise[i-d] )
// => the tap is a plain global reload (L1 hit, same row), no shuffles/smem.
//
// Layout: 16 lanes per row (float4 each), 2 rows per warp, 4-step half-warp
// reduction for the RMS.

#define N_ROWS (32 * 2000)

__global__ __launch_bounds__(256) void tcn_kernel(
    const float4* __restrict__ params,  // [N_ROWS] float4
    const float*  __restrict__ noise,   // [N_ROWS, 64]
    float*        __restrict__ out)     // [N_ROWS, 64]
{
    const int tid = blockIdx.x * blockDim.x + threadIdx.x;
    const int row = tid >> 4;          // 16 lanes per row
    const int l   = tid & 15;
    if (row >= N_ROWS) return;

    const float4 p = __ldg(params + row);

    // Strict-rounded ops so the truncated delay matches JAX's unfused fp32 math.
    const float att     = fmaxf(__fmul_rn(16000.0f,
                                __fadd_rn(0.0005f, __fmul_rn(p.x, 0.0495f))), 1.0f);
    const float energy  = p.y;
    const float tilt    = __fmaf_rn(p.z, 2.0f, -1.0f);
    const float bw      = __fadd_rn(0.05f, __fmul_rn(p.w, 0.95f));
    int delay = (int)__fmul_rn(64.0f, __fadd_rn(0.5f, __fmul_rn(0.5f, bw)));
    delay = min(max(delay, 1), 480);   // effectively [33, 63]

    const float inv_att = __frcp_rn(att);

    const int    i0   = l << 2;                       // first element index
    const size_t base = (size_t)row * 64 + i0;
    const float4 n    = *reinterpret_cast<const float4*>(noise + base);

    // Envelope via recurrence: env(i0+k) = E * r^k.
    const float r  = __expf(-inv_att);
    const float e0 = __expf(-(float)i0 * inv_att) * energy;
    const float e1 = e0 * r;
    const float e2 = e1 * r;
    const float e3 = e2 * r;

    // Tap factor: tilt * exp(delay/att)  (delay/att <= 63/8, no overflow).
    const float tf = tilt * __expf((float)delay * inv_att);

    // Tap reloads (same row, elements i-delay in [0,30] -> L1 hits).
    const float* np = noise + (base - delay);
    const float m0 = (i0 + 0 >= delay) ? np[0] : 0.0f;
    const float m1 = (i0 + 1 >= delay) ? np[1] : 0.0f;
    const float m2 = (i0 + 2 >= delay) ? np[2] : 0.0f;
    const float m3 = (i0 + 3 >= delay) ? np[3] : 0.0f;

    const float y0 = e0 * __fmaf_rn(tf, m0, n.x);
    const float y1 = e1 * __fmaf_rn(tf, m1, n.y);
    const float y2 = e2 * __fmaf_rn(tf, m2, n.z);
    const float y3 = e3 * __fmaf_rn(tf, m3, n.w);

    // Sum of squares over the 16-lane row group.
    float ss = y0 * y0 + y1 * y1 + y2 * y2 + y3 * y3;
    ss += __shfl_xor_sync(0xFFFFFFFFu, ss, 8);
    ss += __shfl_xor_sync(0xFFFFFFFFu, ss, 4);
    ss += __shfl_xor_sync(0xFFFFFFFFu, ss, 2);
    ss += __shfl_xor_sync(0xFFFFFFFFu, ss, 1);

    const float inv_rms = rsqrtf(ss * (1.0f / 64.0f) + 1e-5f);

    float4 o;
    o.x = y0 * inv_rms;
    o.y = y1 * inv_rms;
    o.z = y2 * inv_rms;
    o.w = y3 * inv_rms;
    *reinterpret_cast<float4*>(out + base) = o;
}

extern "C" void kernel_launch(void* const* d_in, const int* in_sizes, int n_in,
                              void* d_out, int out_size)
{
    const float4* params = (const float4*)d_in[0];  // [32,2000,4]
    const float*  noise  = (const float*)d_in[1];   // [32,2000,64]
    float* out = (float*)d_out;                     // [32, 2000*64]

    const int threads = 256;                        // 16 rows per block
    const int blocks  = (N_ROWS * 16 + threads - 1) / threads;  // 4000
    tcn_kernel<<<blocks, threads>>>(params, noise, out);
}